// round 13
// baseline (speedup 1.0000x reference)
#include <cuda_runtime.h>
#include <cuda_bf16.h>
#include <cstdint>

#define N_ATOMS 32768
#define D_DIM 1024
#define H_DIM 1024
#define E_NUM 4
#define BM 128
#define BN 128
#define BK 64
#define NSTAGE 3
#define KSTAGES (D_DIM / BK)               // 16
#define NPAD_MAX (N_ATOMS + E_NUM * BM)    // 33280
#define MAXTILES (NPAD_MAX / BM)           // 260
#define NFINALBLK (NPAD_MAX / 8)           // 4160

// smem: per stage A 128x128B = 16KB, B 64x256B = 16KB
#define STAGE_BYTES 32768
#define SMEM_TOTAL (NSTAGE * STAGE_BYTES)  // 98304

// ---------------- device scratch (no allocation allowed) ----------------
__device__ __align__(256) __nv_bfloat16 g_Xg[(size_t)NPAD_MAX * D_DIM];
__device__ __align__(256) __nv_bfloat16 g_H1[(size_t)NPAD_MAX * H_DIM];
__device__ __align__(256) __nv_bfloat16 g_H2[(size_t)NPAD_MAX * H_DIM];
__device__ __align__(256) __nv_bfloat16 g_Wb1[(size_t)E_NUM * D_DIM * H_DIM]; // [e][k][n]
__device__ __align__(256) __nv_bfloat16 g_Wb2[(size_t)E_NUM * H_DIM * H_DIM]; // [e][k][n]
__device__ int g_perm[NPAD_MAX];
__device__ int g_cursor[E_NUM];
__device__ int g_poff[E_NUM + 1];
__device__ int g_validEnd[E_NUM];
__device__ float g_partials[NFINALBLK];

__device__ __forceinline__ uint32_t smem_u32(const void* p) {
    return (uint32_t)__cvta_generic_to_shared(p);
}
#define CP16(dst, src) \
    asm volatile("cp.async.cg.shared.global [%0], [%1], 16;" :: "r"(dst), "l"(src))

// ---------------- bookkeeping ----------------
// single block: count symbols, compute padded segment offsets (fuses zero+count+setup)
__global__ void count_setup_kernel(const int* __restrict__ sym) {
    __shared__ int cnt[E_NUM];
    int tid = threadIdx.x, lane = tid & 31;
    if (tid < E_NUM) cnt[tid] = 0;
    __syncthreads();
    for (int i = tid; i < N_ATOMS; i += 1024) {
        int s = sym[i];
#pragma unroll
        for (int e = 0; e < E_NUM; e++) {
            unsigned m = __ballot_sync(0xffffffffu, s == e);
            if (lane == 0 && m) atomicAdd(&cnt[e], __popc(m));
        }
    }
    __syncthreads();
    if (tid == 0) {
        int off = 0;
        for (int e = 0; e < E_NUM; e++) {
            g_poff[e] = off;
            g_cursor[e] = off;
            g_validEnd[e] = off + cnt[e];
            off += ((cnt[e] + BM - 1) / BM) * BM;
        }
        g_poff[E_NUM] = off;
    }
}

__global__ void scatter_kernel(const int* __restrict__ sym) {
    int i = blockIdx.x * blockDim.x + threadIdx.x;
    int lane = threadIdx.x & 31;
    int s = (i < N_ATOMS) ? sym[i] : -1;
#pragma unroll
    for (int e = 0; e < E_NUM; e++) {
        unsigned m = __ballot_sync(0xffffffffu, s == e);
        if (s == e) {
            int leader = __ffs(m) - 1;
            int base = 0;
            if (lane == leader) base = atomicAdd(&g_cursor[e], __popc(m));
            base = __shfl_sync(m, base, leader);
            int pos = base + __popc(m & ((1u << lane) - 1u));
            g_perm[pos] = i;
        }
    }
}

// gather + fp32->bf16, zero padding rows
__global__ void gather_kernel(const float* __restrict__ features) {
    int row = blockIdx.x;
    if (row >= g_poff[E_NUM]) return;
    int e = 0;
#pragma unroll
    for (int q = 1; q < E_NUM; q++)
        if (row >= g_poff[q]) e = q;

    __nv_bfloat16* dst = g_Xg + (size_t)row * D_DIM;
    int k = threadIdx.x * 8;
    uint4 outv;
    if (row < g_validEnd[e]) {
        const float* src = features + (size_t)g_perm[row] * D_DIM + k;
        float4 f0 = *(const float4*)(src);
        float4 f1 = *(const float4*)(src + 4);
        __nv_bfloat162 a = __floats2bfloat162_rn(f0.x, f0.y);
        __nv_bfloat162 b = __floats2bfloat162_rn(f0.z, f0.w);
        __nv_bfloat162 c = __floats2bfloat162_rn(f1.x, f1.y);
        __nv_bfloat162 d = __floats2bfloat162_rn(f1.z, f1.w);
        outv.x = *(uint32_t*)&a; outv.y = *(uint32_t*)&b;
        outv.z = *(uint32_t*)&c; outv.w = *(uint32_t*)&d;
    } else {
        outv.x = outv.y = outv.z = outv.w = 0u;
    }
    *(uint4*)&dst[k] = outv;
}

// straight fp32 -> bf16 convert of both weight tensors (layout preserved: [e][k][n])
__global__ void convw_kernel(const float* __restrict__ W1, const float* __restrict__ W2) {
    size_t i = ((size_t)blockIdx.x * blockDim.x + threadIdx.x) * 4;
    float4 v1 = *(const float4*)(W1 + i);
    float4 v2 = *(const float4*)(W2 + i);
    __nv_bfloat162 a1 = __floats2bfloat162_rn(v1.x, v1.y);
    __nv_bfloat162 b1 = __floats2bfloat162_rn(v1.z, v1.w);
    __nv_bfloat162 a2 = __floats2bfloat162_rn(v2.x, v2.y);
    __nv_bfloat162 b2 = __floats2bfloat162_rn(v2.z, v2.w);
    *(uint2*)(g_Wb1 + i) = make_uint2(*(uint32_t*)&a1, *(uint32_t*)&b1);
    *(uint2*)(g_Wb2 + i) = make_uint2(*(uint32_t*)&a2, *(uint32_t*)&b2);
}

// ---------------- GEMM: Out = relu(A @ W + bias) ----------------
// A: [rows][1024] bf16 k-contig. W: [e][k][n] bf16 n-contig. Out: [rows][1024] bf16.
// CTA 128x128, BK=64, 3-stage cp.async ring, ldmatrix fragments.
__global__ void __launch_bounds__(256)
gemm_kernel(int which, const float* __restrict__ bias) {
    const int total = g_poff[E_NUM];
    const int rt = blockIdx.y;
    if (rt * BM >= total) return;
    int e = 0;
#pragma unroll
    for (int q = 1; q < E_NUM; q++)
        if (rt * BM >= g_poff[q]) e = q;

    const __nv_bfloat16* __restrict__ A = which ? g_H1 : g_Xg;
    const __nv_bfloat16* __restrict__ W = which ? g_Wb2 : g_Wb1;
    __nv_bfloat16* __restrict__ Out = which ? g_H2 : g_H1;

    const int row0 = rt * BM;
    const int n0 = blockIdx.x * BN;
    const __nv_bfloat16* Ab = A + (size_t)row0 * D_DIM;
    const __nv_bfloat16* Wb = W + (size_t)e * (D_DIM * H_DIM) + n0;

    extern __shared__ char smem[];
    const uint32_t sb = smem_u32(smem);
    const int tid = threadIdx.x;
    const int lane = tid & 31;
    const int warp = tid >> 5;
    const int wm = warp >> 1;   // 0..3 -> 32-row slice
    const int wn = warp & 1;    // 0..1 -> 64-col slice

    float acc[2][8][4];
#pragma unroll
    for (int i = 0; i < 2; i++)
#pragma unroll
        for (int j = 0; j < 8; j++)
#pragma unroll
            for (int k = 0; k < 4; k++) acc[i][j][k] = 0.f;

    // ---- cp.async producers: A tile 128 rows x 128B, B tile 64 rows x 256B ----
    auto load_stage = [&](int slot, int kt) {
        const uint32_t abase = sb + slot * STAGE_BYTES;
        const uint32_t bbase = abase + 16384;
#pragma unroll
        for (int i = 0; i < 4; i++) {
            int cid = tid + i * 256;            // 0..1023
            // A: row = cid>>3 (0..127), chunk c = cid&7
            {
                int r = cid >> 3, c = cid & 7;
                const __nv_bfloat16* src = Ab + (size_t)r * D_DIM + kt * BK + c * 8;
                uint32_t dst = abase + r * 128 + (((uint32_t)(c ^ (r & 7))) << 4);
                CP16(dst, src);
            }
            // B: row k = cid>>4 (0..63), sub = cid&15 -> block b (0/1), chunk ch
            {
                int k = cid >> 4, sub = cid & 15;
                int b = sub >> 3, ch = sub & 7;
                const __nv_bfloat16* src = Wb + (size_t)(kt * BK + k) * H_DIM + b * 64 + ch * 8;
                uint32_t dst = bbase + k * 256 + b * 128 + (((uint32_t)(ch ^ (k & 7))) << 4);
                CP16(dst, src);
            }
        }
        asm volatile("cp.async.commit_group;");
    };

    load_stage(0, 0);
    load_stage(1, 1);

    // ldmatrix lane addressing components
    const int a_r = lane & 15;                 // row within m16
    const uint32_t a_cb = (uint32_t)(lane >> 4) * 16;  // 0 or 16 bytes
    const int b_j = lane >> 3, b_jr = lane & 7;
    const int b_krow = b_jr + (b_j & 1) * 8;   // k within k16
    const uint32_t b_nb_half = (uint32_t)(b_j >> 1) * 16;

    for (int kt = 0; kt < KSTAGES; kt++) {
        const int slot = kt % NSTAGE;
        if (kt + 2 < KSTAGES) load_stage((kt + 2) % NSTAGE, kt + 2);
        if (kt + 2 < KSTAGES)      asm volatile("cp.async.wait_group 2;");
        else if (kt + 1 < KSTAGES) asm volatile("cp.async.wait_group 1;");
        else                       asm volatile("cp.async.wait_group 0;");
        __syncthreads();

        const uint32_t abase = sb + slot * STAGE_BYTES;
        const uint32_t bbase = abase + 16384;

#pragma unroll
        for (int kk = 0; kk < BK; kk += 16) {
            // A fragments: 2x ldmatrix.x4
            uint32_t a[2][4];
#pragma unroll
            for (int mt = 0; mt < 2; mt++) {
                int row = wm * 32 + mt * 16 + a_r;
                uint32_t byte = (uint32_t)kk * 2 + a_cb;
                uint32_t addr = abase + row * 128 + ((((byte >> 4) ^ (uint32_t)(row & 7))) << 4);
                asm volatile("ldmatrix.sync.aligned.m8n8.x4.shared.b16 {%0,%1,%2,%3}, [%4];"
                             : "=r"(a[mt][0]), "=r"(a[mt][1]), "=r"(a[mt][2]), "=r"(a[mt][3])
                             : "r"(addr));
            }
            // B fragments: 4x ldmatrix.x4.trans -> 8 (k16,n8) frags
            uint32_t bf[8][2];
#pragma unroll
            for (int p = 0; p < 4; p++) {
                int k = kk + b_krow;
                uint32_t nbyte = (uint32_t)wn * 128 + (uint32_t)p * 32 + b_nb_half;
                uint32_t addr = bbase + k * 256 + (nbyte >> 7) * 128 +
                                ((((nbyte >> 4) & 7) ^ (uint32_t)(k & 7)) << 4);
                uint32_t t0, t1, t2, t3;
                asm volatile("ldmatrix.sync.aligned.m8n8.x4.trans.shared.b16 {%0,%1,%2,%3}, [%4];"
                             : "=r"(t0), "=r"(t1), "=r"(t2), "=r"(t3) : "r"(addr));
                bf[p * 2][0] = t0; bf[p * 2][1] = t1;
                bf[p * 2 + 1][0] = t2; bf[p * 2 + 1][1] = t3;
            }
#pragma unroll
            for (int mt = 0; mt < 2; mt++)
#pragma unroll
                for (int nt = 0; nt < 8; nt++) {
                    asm volatile(
                        "mma.sync.aligned.m16n8k16.row.col.f32.bf16.bf16.f32 "
                        "{%0,%1,%2,%3}, {%4,%5,%6,%7}, {%8,%9}, {%0,%1,%2,%3};"
                        : "+f"(acc[mt][nt][0]), "+f"(acc[mt][nt][1]),
                          "+f"(acc[mt][nt][2]), "+f"(acc[mt][nt][3])
                        : "r"(a[mt][0]), "r"(a[mt][1]), "r"(a[mt][2]), "r"(a[mt][3]),
                          "r"(bf[nt][0]), "r"(bf[nt][1]));
                }
        }
        __syncthreads();
    }

    // ---- epilogue: bias + relu -> bf16 ----
    const float* bp = bias + e * H_DIM;
#pragma unroll
    for (int mt = 0; mt < 2; mt++) {
        const int r = row0 + wm * 32 + mt * 16 + (lane >> 2);
#pragma unroll
        for (int nt = 0; nt < 8; nt++) {
            const int cidx = n0 + wn * 64 + nt * 8 + (lane & 3) * 2;
            float bb0 = bp[cidx], bb1 = bp[cidx + 1];
            float v0 = fmaxf(acc[mt][nt][0] + bb0, 0.f);
            float v1 = fmaxf(acc[mt][nt][1] + bb1, 0.f);
            float v2 = fmaxf(acc[mt][nt][2] + bb0, 0.f);
            float v3 = fmaxf(acc[mt][nt][3] + bb1, 0.f);
            __nv_bfloat162 p01 = __floats2bfloat162_rn(v0, v1);
            __nv_bfloat162 p23 = __floats2bfloat162_rn(v2, v3);
            *(uint32_t*)&Out[(size_t)r * H_DIM + cidx] = *(uint32_t*)&p01;
            *(uint32_t*)&Out[(size_t)(r + 8) * H_DIM + cidx] = *(uint32_t*)&p23;
        }
    }
}

// ---------------- layer 3 + reductions ----------------
__global__ void final_kernel(const float* __restrict__ W3, const float* __restrict__ b3,
                             const float* __restrict__ slope, const float* __restrict__ intercept) {
    int warp = threadIdx.x >> 5, lane = threadIdx.x & 31;
    int row = blockIdx.x * 8 + warp;
    float contrib = 0.f;
    if (row < g_poff[E_NUM]) {
        int e = 0;
#pragma unroll
        for (int q = 1; q < E_NUM; q++)
            if (row >= g_poff[q]) e = q;
        if (row < g_validEnd[e]) {
            const __nv_bfloat16* h = g_H2 + (size_t)row * H_DIM;
            const float* w = W3 + e * H_DIM;
            float s = 0.f;
#pragma unroll
            for (int i = 0; i < 4; i++) {
                int k = lane * 8 + i * 256;
                uint4 hv = *(const uint4*)&h[k];
                float4 w0 = *(const float4*)&w[k];
                float4 w1 = *(const float4*)&w[k + 4];
                __nv_bfloat162 p0 = *reinterpret_cast<const __nv_bfloat162*>(&hv.x);
                __nv_bfloat162 p1 = *reinterpret_cast<const __nv_bfloat162*>(&hv.y);
                __nv_bfloat162 p2 = *reinterpret_cast<const __nv_bfloat162*>(&hv.z);
                __nv_bfloat162 p3 = *reinterpret_cast<const __nv_bfloat162*>(&hv.w);
                s += __bfloat162float(p0.x) * w0.x + __bfloat162float(p0.y) * w0.y;
                s += __bfloat162float(p1.x) * w0.z + __bfloat162float(p1.y) * w0.w;
                s += __bfloat162float(p2.x) * w1.x + __bfloat162float(p2.y) * w1.y;
                s += __bfloat162float(p3.x) * w1.z + __bfloat162float(p3.y) * w1.w;
            }
#pragma unroll
            for (int o = 16; o > 0; o >>= 1) s += __shfl_xor_sync(0xffffffffu, s, o);
            contrib = slope[e] * (s + b3[e]) + intercept[e];
        }
    }
    __shared__ float ws[8];
    if (lane == 0) ws[warp] = contrib;
    __syncthreads();
    if (threadIdx.x == 0) {
        float t2 = 0.f;
#pragma unroll
        for (int i = 0; i < 8; i++) t2 += ws[i];
        g_partials[blockIdx.x] = t2;
    }
}

__global__ void reduce_kernel(float* __restrict__ out) {
    __shared__ float sm[256];
    float s = 0.f;
    for (int i = threadIdx.x; i < NFINALBLK; i += 256) s += g_partials[i];
    sm[threadIdx.x] = s;
    __syncthreads();
    for (int o = 128; o > 0; o >>= 1) {
        if (threadIdx.x < o) sm[threadIdx.x] += sm[threadIdx.x + o];
        __syncthreads();
    }
    if (threadIdx.x == 0) out[0] = sm[0];
}

// ---------------- launch ----------------
extern "C" void kernel_launch(void* const* d_in, const int* in_sizes, int n_in,
                              void* d_out, int out_size) {
    const float* features  = (const float*)d_in[0];
    const int*   sym       = (const int*)d_in[1];
    const float* W1        = (const float*)d_in[2];
    const float* b1        = (const float*)d_in[3];
    const float* W2        = (const float*)d_in[4];
    const float* b2        = (const float*)d_in[5];
    const float* W3        = (const float*)d_in[6];
    const float* b3        = (const float*)d_in[7];
    const float* slope     = (const float*)d_in[8];
    const float* intercept = (const float*)d_in[9];
    float* out = (float*)d_out;
    (void)in_sizes; (void)n_in; (void)out_size;

    static bool attr_set = false;
    if (!attr_set) {  // host-side idempotent attribute set (no device work)
        cudaFuncSetAttribute(gemm_kernel,
                             cudaFuncAttributeMaxDynamicSharedMemorySize, SMEM_TOTAL);
        attr_set = true;
    }

    // launch order arranged so ncu (-s 5 -c 1) profiles gemm #2 (index 5)
    count_setup_kernel<<<1, 1024>>>(sym);                              // 0
    scatter_kernel<<<N_ATOMS / 256, 256>>>(sym);                       // 1
    gather_kernel<<<NPAD_MAX, 128>>>(features);                        // 2
    convw_kernel<<<(E_NUM * D_DIM * H_DIM) / 4 / 256, 256>>>(W1, W2);  // 3
    gemm_kernel<<<dim3(H_DIM / BN, MAXTILES), 256, SMEM_TOTAL>>>(0, b1); // 4
    gemm_kernel<<<dim3(H_DIM / BN, MAXTILES), 256, SMEM_TOTAL>>>(1, b2); // 5
    final_kernel<<<NFINALBLK, 256>>>(W3, b3, slope, intercept);        // 6
    reduce_kernel<<<1, 256>>>(out);                                    // 7
}

// round 14
// speedup vs baseline: 1.0048x; 1.0048x over previous
#include <cuda_runtime.h>
#include <cuda_bf16.h>
#include <cstdint>

#define N_ATOMS 32768
#define D_DIM 1024
#define H_DIM 1024
#define E_NUM 4
#define BM 128
#define BN 128
#define BK 64
#define NSTAGE 3
#define KSTAGES (D_DIM / BK)               // 16
#define NPAD_MAX (N_ATOMS + E_NUM * BM)    // 33280
#define MAXTILES (NPAD_MAX / BM)           // 260
#define NFINALBLK (NPAD_MAX / 8)           // 4160

// smem: per stage A 128x128B = 16KB, B 64x256B = 16KB
#define STAGE_BYTES 32768
#define SMEM_TOTAL (NSTAGE * STAGE_BYTES)  // 98304

// ---------------- device scratch (no allocation allowed) ----------------
__device__ __align__(256) __nv_bfloat16 g_Xg[(size_t)NPAD_MAX * D_DIM];
__device__ __align__(256) __nv_bfloat16 g_H1[(size_t)NPAD_MAX * H_DIM];
__device__ __align__(256) __nv_bfloat16 g_H2[(size_t)NPAD_MAX * H_DIM];
__device__ __align__(256) __nv_bfloat16 g_Wb1[(size_t)E_NUM * D_DIM * H_DIM]; // [e][k][n]
__device__ __align__(256) __nv_bfloat16 g_Wb2[(size_t)E_NUM * H_DIM * H_DIM]; // [e][k][n]
__device__ int g_perm[NPAD_MAX];
__device__ int g_cursor[E_NUM];
__device__ int g_poff[E_NUM + 1];
__device__ int g_validEnd[E_NUM];
__device__ float g_partials[NFINALBLK];

__device__ __forceinline__ uint32_t smem_u32(const void* p) {
    return (uint32_t)__cvta_generic_to_shared(p);
}
#define CP16(dst, src) \
    asm volatile("cp.async.cg.shared.global [%0], [%1], 16;" :: "r"(dst), "l"(src))

// ---------------- bookkeeping ----------------
// single block: count symbols, compute padded segment offsets (fuses zero+count+setup)
__global__ void count_setup_kernel(const int* __restrict__ sym) {
    __shared__ int cnt[E_NUM];
    int tid = threadIdx.x, lane = tid & 31;
    if (tid < E_NUM) cnt[tid] = 0;
    __syncthreads();
    for (int i = tid; i < N_ATOMS; i += 1024) {
        int s = sym[i];
#pragma unroll
        for (int e = 0; e < E_NUM; e++) {
            unsigned m = __ballot_sync(0xffffffffu, s == e);
            if (lane == 0 && m) atomicAdd(&cnt[e], __popc(m));
        }
    }
    __syncthreads();
    if (tid == 0) {
        int off = 0;
        for (int e = 0; e < E_NUM; e++) {
            g_poff[e] = off;
            g_cursor[e] = off;
            g_validEnd[e] = off + cnt[e];
            off += ((cnt[e] + BM - 1) / BM) * BM;
        }
        g_poff[E_NUM] = off;
    }
}

__global__ void scatter_kernel(const int* __restrict__ sym) {
    int i = blockIdx.x * blockDim.x + threadIdx.x;
    int lane = threadIdx.x & 31;
    int s = (i < N_ATOMS) ? sym[i] : -1;
#pragma unroll
    for (int e = 0; e < E_NUM; e++) {
        unsigned m = __ballot_sync(0xffffffffu, s == e);
        if (s == e) {
            int leader = __ffs(m) - 1;
            int base = 0;
            if (lane == leader) base = atomicAdd(&g_cursor[e], __popc(m));
            base = __shfl_sync(m, base, leader);
            int pos = base + __popc(m & ((1u << lane) - 1u));
            g_perm[pos] = i;
        }
    }
}

// gather + fp32->bf16, zero padding rows
__global__ void gather_kernel(const float* __restrict__ features) {
    int row = blockIdx.x;
    if (row >= g_poff[E_NUM]) return;
    int e = 0;
#pragma unroll
    for (int q = 1; q < E_NUM; q++)
        if (row >= g_poff[q]) e = q;

    __nv_bfloat16* dst = g_Xg + (size_t)row * D_DIM;
    int k = threadIdx.x * 8;
    uint4 outv;
    if (row < g_validEnd[e]) {
        const float* src = features + (size_t)g_perm[row] * D_DIM + k;
        float4 f0 = *(const float4*)(src);
        float4 f1 = *(const float4*)(src + 4);
        __nv_bfloat162 a = __floats2bfloat162_rn(f0.x, f0.y);
        __nv_bfloat162 b = __floats2bfloat162_rn(f0.z, f0.w);
        __nv_bfloat162 c = __floats2bfloat162_rn(f1.x, f1.y);
        __nv_bfloat162 d = __floats2bfloat162_rn(f1.z, f1.w);
        outv.x = *(uint32_t*)&a; outv.y = *(uint32_t*)&b;
        outv.z = *(uint32_t*)&c; outv.w = *(uint32_t*)&d;
    } else {
        outv.x = outv.y = outv.z = outv.w = 0u;
    }
    *(uint4*)&dst[k] = outv;
}

// straight fp32 -> bf16 convert of both weight tensors (layout preserved: [e][k][n])
__global__ void convw_kernel(const float* __restrict__ W1, const float* __restrict__ W2) {
    size_t i = ((size_t)blockIdx.x * blockDim.x + threadIdx.x) * 4;
    float4 v1 = *(const float4*)(W1 + i);
    float4 v2 = *(const float4*)(W2 + i);
    __nv_bfloat162 a1 = __floats2bfloat162_rn(v1.x, v1.y);
    __nv_bfloat162 b1 = __floats2bfloat162_rn(v1.z, v1.w);
    __nv_bfloat162 a2 = __floats2bfloat162_rn(v2.x, v2.y);
    __nv_bfloat162 b2 = __floats2bfloat162_rn(v2.z, v2.w);
    *(uint2*)(g_Wb1 + i) = make_uint2(*(uint32_t*)&a1, *(uint32_t*)&b1);
    *(uint2*)(g_Wb2 + i) = make_uint2(*(uint32_t*)&a2, *(uint32_t*)&b2);
}

// ---------------- GEMM: Out = relu(A @ W + bias) ----------------
// A: [rows][1024] bf16 k-contig. W: [e][k][n] bf16 n-contig. Out: [rows][1024] bf16.
// CTA 128x128, BK=64, 3-stage cp.async ring, ldmatrix fragments.
__global__ void __launch_bounds__(256)
gemm_kernel(int which, const float* __restrict__ bias) {
    const int total = g_poff[E_NUM];
    const int rt = blockIdx.y;
    if (rt * BM >= total) return;
    int e = 0;
#pragma unroll
    for (int q = 1; q < E_NUM; q++)
        if (rt * BM >= g_poff[q]) e = q;

    const __nv_bfloat16* __restrict__ A = which ? g_H1 : g_Xg;
    const __nv_bfloat16* __restrict__ W = which ? g_Wb2 : g_Wb1;
    __nv_bfloat16* __restrict__ Out = which ? g_H2 : g_H1;

    const int row0 = rt * BM;
    const int n0 = blockIdx.x * BN;
    const __nv_bfloat16* Ab = A + (size_t)row0 * D_DIM;
    const __nv_bfloat16* Wb = W + (size_t)e * (D_DIM * H_DIM) + n0;

    extern __shared__ char smem[];
    const uint32_t sb = smem_u32(smem);
    const int tid = threadIdx.x;
    const int lane = tid & 31;
    const int warp = tid >> 5;
    const int wm = warp >> 1;   // 0..3 -> 32-row slice
    const int wn = warp & 1;    // 0..1 -> 64-col slice

    float acc[2][8][4];
#pragma unroll
    for (int i = 0; i < 2; i++)
#pragma unroll
        for (int j = 0; j < 8; j++)
#pragma unroll
            for (int k = 0; k < 4; k++) acc[i][j][k] = 0.f;

    // ---- cp.async producers: A tile 128 rows x 128B, B tile 64 rows x 256B ----
    auto load_stage = [&](int slot, int kt) {
        const uint32_t abase = sb + slot * STAGE_BYTES;
        const uint32_t bbase = abase + 16384;
#pragma unroll
        for (int i = 0; i < 4; i++) {
            int cid = tid + i * 256;            // 0..1023
            // A: row = cid>>3 (0..127), chunk c = cid&7
            {
                int r = cid >> 3, c = cid & 7;
                const __nv_bfloat16* src = Ab + (size_t)r * D_DIM + kt * BK + c * 8;
                uint32_t dst = abase + r * 128 + (((uint32_t)(c ^ (r & 7))) << 4);
                CP16(dst, src);
            }
            // B: row k = cid>>4 (0..63), sub = cid&15 -> block b (0/1), chunk ch
            {
                int k = cid >> 4, sub = cid & 15;
                int b = sub >> 3, ch = sub & 7;
                const __nv_bfloat16* src = Wb + (size_t)(kt * BK + k) * H_DIM + b * 64 + ch * 8;
                uint32_t dst = bbase + k * 256 + b * 128 + (((uint32_t)(ch ^ (k & 7))) << 4);
                CP16(dst, src);
            }
        }
        asm volatile("cp.async.commit_group;");
    };

    load_stage(0, 0);
    load_stage(1, 1);

    // ldmatrix lane addressing components
    const int a_r = lane & 15;                 // row within m16
    const uint32_t a_cb = (uint32_t)(lane >> 4) * 16;  // 0 or 16 bytes
    const int b_j = lane >> 3, b_jr = lane & 7;
    const int b_krow = b_jr + (b_j & 1) * 8;   // k within k16
    const uint32_t b_nb_half = (uint32_t)(b_j >> 1) * 16;

    for (int kt = 0; kt < KSTAGES; kt++) {
        const int slot = kt % NSTAGE;
        if (kt + 2 < KSTAGES) load_stage((kt + 2) % NSTAGE, kt + 2);
        if (kt + 2 < KSTAGES)      asm volatile("cp.async.wait_group 2;");
        else if (kt + 1 < KSTAGES) asm volatile("cp.async.wait_group 1;");
        else                       asm volatile("cp.async.wait_group 0;");
        __syncthreads();

        const uint32_t abase = sb + slot * STAGE_BYTES;
        const uint32_t bbase = abase + 16384;

#pragma unroll
        for (int kk = 0; kk < BK; kk += 16) {
            // A fragments: 2x ldmatrix.x4
            uint32_t a[2][4];
#pragma unroll
            for (int mt = 0; mt < 2; mt++) {
                int row = wm * 32 + mt * 16 + a_r;
                uint32_t byte = (uint32_t)kk * 2 + a_cb;
                uint32_t addr = abase + row * 128 + ((((byte >> 4) ^ (uint32_t)(row & 7))) << 4);
                asm volatile("ldmatrix.sync.aligned.m8n8.x4.shared.b16 {%0,%1,%2,%3}, [%4];"
                             : "=r"(a[mt][0]), "=r"(a[mt][1]), "=r"(a[mt][2]), "=r"(a[mt][3])
                             : "r"(addr));
            }
            // B fragments: 4x ldmatrix.x4.trans -> 8 (k16,n8) frags
            uint32_t bf[8][2];
#pragma unroll
            for (int p = 0; p < 4; p++) {
                int k = kk + b_krow;
                uint32_t nbyte = (uint32_t)wn * 128 + (uint32_t)p * 32 + b_nb_half;
                uint32_t addr = bbase + k * 256 + (nbyte >> 7) * 128 +
                                ((((nbyte >> 4) & 7) ^ (uint32_t)(k & 7)) << 4);
                uint32_t t0, t1, t2, t3;
                asm volatile("ldmatrix.sync.aligned.m8n8.x4.trans.shared.b16 {%0,%1,%2,%3}, [%4];"
                             : "=r"(t0), "=r"(t1), "=r"(t2), "=r"(t3) : "r"(addr));
                bf[p * 2][0] = t0; bf[p * 2][1] = t1;
                bf[p * 2 + 1][0] = t2; bf[p * 2 + 1][1] = t3;
            }
#pragma unroll
            for (int mt = 0; mt < 2; mt++)
#pragma unroll
                for (int nt = 0; nt < 8; nt++) {
                    asm volatile(
                        "mma.sync.aligned.m16n8k16.row.col.f32.bf16.bf16.f32 "
                        "{%0,%1,%2,%3}, {%4,%5,%6,%7}, {%8,%9}, {%0,%1,%2,%3};"
                        : "+f"(acc[mt][nt][0]), "+f"(acc[mt][nt][1]),
                          "+f"(acc[mt][nt][2]), "+f"(acc[mt][nt][3])
                        : "r"(a[mt][0]), "r"(a[mt][1]), "r"(a[mt][2]), "r"(a[mt][3]),
                          "r"(bf[nt][0]), "r"(bf[nt][1]));
                }
        }
        __syncthreads();
    }

    // ---- epilogue: bias + relu -> bf16 ----
    const float* bp = bias + e * H_DIM;
#pragma unroll
    for (int mt = 0; mt < 2; mt++) {
        const int r = row0 + wm * 32 + mt * 16 + (lane >> 2);
#pragma unroll
        for (int nt = 0; nt < 8; nt++) {
            const int cidx = n0 + wn * 64 + nt * 8 + (lane & 3) * 2;
            float bb0 = bp[cidx], bb1 = bp[cidx + 1];
            float v0 = fmaxf(acc[mt][nt][0] + bb0, 0.f);
            float v1 = fmaxf(acc[mt][nt][1] + bb1, 0.f);
            float v2 = fmaxf(acc[mt][nt][2] + bb0, 0.f);
            float v3 = fmaxf(acc[mt][nt][3] + bb1, 0.f);
            __nv_bfloat162 p01 = __floats2bfloat162_rn(v0, v1);
            __nv_bfloat162 p23 = __floats2bfloat162_rn(v2, v3);
            *(uint32_t*)&Out[(size_t)r * H_DIM + cidx] = *(uint32_t*)&p01;
            *(uint32_t*)&Out[(size_t)(r + 8) * H_DIM + cidx] = *(uint32_t*)&p23;
        }
    }
}

// ---------------- layer 3 + reductions ----------------
__global__ void final_kernel(const float* __restrict__ W3, const float* __restrict__ b3,
                             const float* __restrict__ slope, const float* __restrict__ intercept) {
    int warp = threadIdx.x >> 5, lane = threadIdx.x & 31;
    int row = blockIdx.x * 8 + warp;
    float contrib = 0.f;
    if (row < g_poff[E_NUM]) {
        int e = 0;
#pragma unroll
        for (int q = 1; q < E_NUM; q++)
            if (row >= g_poff[q]) e = q;
        if (row < g_validEnd[e]) {
            const __nv_bfloat16* h = g_H2 + (size_t)row * H_DIM;
            const float* w = W3 + e * H_DIM;
            float s = 0.f;
#pragma unroll
            for (int i = 0; i < 4; i++) {
                int k = lane * 8 + i * 256;
                uint4 hv = *(const uint4*)&h[k];
                float4 w0 = *(const float4*)&w[k];
                float4 w1 = *(const float4*)&w[k + 4];
                __nv_bfloat162 p0 = *reinterpret_cast<const __nv_bfloat162*>(&hv.x);
                __nv_bfloat162 p1 = *reinterpret_cast<const __nv_bfloat162*>(&hv.y);
                __nv_bfloat162 p2 = *reinterpret_cast<const __nv_bfloat162*>(&hv.z);
                __nv_bfloat162 p3 = *reinterpret_cast<const __nv_bfloat162*>(&hv.w);
                s += __bfloat162float(p0.x) * w0.x + __bfloat162float(p0.y) * w0.y;
                s += __bfloat162float(p1.x) * w0.z + __bfloat162float(p1.y) * w0.w;
                s += __bfloat162float(p2.x) * w1.x + __bfloat162float(p2.y) * w1.y;
                s += __bfloat162float(p3.x) * w1.z + __bfloat162float(p3.y) * w1.w;
            }
#pragma unroll
            for (int o = 16; o > 0; o >>= 1) s += __shfl_xor_sync(0xffffffffu, s, o);
            contrib = slope[e] * (s + b3[e]) + intercept[e];
        }
    }
    __shared__ float ws[8];
    if (lane == 0) ws[warp] = contrib;
    __syncthreads();
    if (threadIdx.x == 0) {
        float t2 = 0.f;
#pragma unroll
        for (int i = 0; i < 8; i++) t2 += ws[i];
        g_partials[blockIdx.x] = t2;
    }
}

__global__ void reduce_kernel(float* __restrict__ out) {
    __shared__ float sm[256];
    float s = 0.f;
    for (int i = threadIdx.x; i < NFINALBLK; i += 256) s += g_partials[i];
    sm[threadIdx.x] = s;
    __syncthreads();
    for (int o = 128; o > 0; o >>= 1) {
        if (threadIdx.x < o) sm[threadIdx.x] += sm[threadIdx.x + o];
        __syncthreads();
    }
    if (threadIdx.x == 0) out[0] = sm[0];
}

// ---------------- launch ----------------
extern "C" void kernel_launch(void* const* d_in, const int* in_sizes, int n_in,
                              void* d_out, int out_size) {
    const float* features  = (const float*)d_in[0];
    const int*   sym       = (const int*)d_in[1];
    const float* W1        = (const float*)d_in[2];
    const float* b1        = (const float*)d_in[3];
    const float* W2        = (const float*)d_in[4];
    const float* b2        = (const float*)d_in[5];
    const float* W3        = (const float*)d_in[6];
    const float* b3        = (const float*)d_in[7];
    const float* slope     = (const float*)d_in[8];
    const float* intercept = (const float*)d_in[9];
    float* out = (float*)d_out;
    (void)in_sizes; (void)n_in; (void)out_size;

    static bool attr_set = false;
    if (!attr_set) {  // host-side idempotent attribute set (no device work)
        cudaFuncSetAttribute(gemm_kernel,
                             cudaFuncAttributeMaxDynamicSharedMemorySize, SMEM_TOTAL);
        attr_set = true;
    }

    // launch order arranged so ncu (-s 5 -c 1) profiles gemm #2 (index 5)
    count_setup_kernel<<<1, 1024>>>(sym);                              // 0
    scatter_kernel<<<N_ATOMS / 256, 256>>>(sym);                       // 1
    gather_kernel<<<NPAD_MAX, 128>>>(features);                        // 2
    convw_kernel<<<(E_NUM * D_DIM * H_DIM) / 4 / 256, 256>>>(W1, W2);  // 3
    gemm_kernel<<<dim3(H_DIM / BN, MAXTILES), 256, SMEM_TOTAL>>>(0, b1); // 4
    gemm_kernel<<<dim3(H_DIM / BN, MAXTILES), 256, SMEM_TOTAL>>>(1, b2); // 5
    final_kernel<<<NFINALBLK, 256>>>(W3, b3, slope, intercept);        // 6
    reduce_kernel<<<1, 256>>>(out);                                    // 7
}